// round 7
// baseline (speedup 1.0000x reference)
#include <cuda_runtime.h>
#include <cuda_bf16.h>
#include <stdint.h>
#include <math.h>

#define N_ROWS 65536
#define P_ROWS 2048
#define D_DIM  512

#define BM 128
#define BN 128
#define BK 64            // int8 elements -> 64 bytes per row-chunk
#define STAGES 4
#define K_ITERS (D_DIM / BK)   // 8

// smem geometry: padded 80B row stride (conflict-free ldmatrix, 16B-aligned)
#define ROWB 80
#define TILE_BYTES (128 * ROWB)        // 10240
#define STAGE_BYTES (2 * TILE_BYTES)   // A + B = 20480
#define SMEM_TOTAL (STAGES * STAGE_BYTES)  // 81920

// ---------------- scratch (static device globals; no runtime allocation) ----
__device__ float g_xsq[N_ROWS];
__device__ float g_psq[P_ROWS];
__device__ float g_xscale[N_ROWS];
__device__ float g_pscale[P_ROWS];
__device__ int8_t g_eq[(size_t)N_ROWS * D_DIM];
__device__ int8_t g_pq[(size_t)P_ROWS * D_DIM];

// ---------------- PTX helpers ----------------------------------------------
__device__ __forceinline__ uint32_t smem_u32(const void* p) {
    uint32_t a;
    asm("{ .reg .u64 t; cvta.to.shared.u64 t, %1; cvt.u32.u64 %0, t; }" : "=r"(a) : "l"(p));
    return a;
}

#define CP_ASYNC16(dst, src) \
    asm volatile("cp.async.cg.shared.global [%0], [%1], 16;" :: "r"(dst), "l"(src) : "memory")
#define CP_COMMIT() asm volatile("cp.async.commit_group;" ::: "memory")
#define CP_WAIT(n)  asm volatile("cp.async.wait_group %0;" :: "n"(n) : "memory")

#define LDMATRIX_X4(r0, r1, r2, r3, addr) \
    asm volatile("ldmatrix.sync.aligned.m8n8.x4.shared.b16 {%0,%1,%2,%3}, [%4];" \
        : "=r"(r0), "=r"(r1), "=r"(r2), "=r"(r3) : "r"(addr))

// m16n8k32 int8 -> s32. A: 4 regs, B: 2 regs, C/D: 4 regs.
#define MMA_16832_S8(c0, c1, c2, c3, a0, a1, a2, a3, b0, b1) \
    asm volatile("mma.sync.aligned.m16n8k32.row.col.s32.s8.s8.s32 " \
        "{%0,%1,%2,%3}, {%4,%5,%6,%7}, {%8,%9}, {%0,%1,%2,%3};" \
        : "+r"(c0), "+r"(c1), "+r"(c2), "+r"(c3) \
        : "r"(a0), "r"(a1), "r"(a2), "r"(a3), "r"(b0), "r"(b1))

// ---------------- convert fp32 -> int8 (per-row absmax) + norms -------------
__device__ __forceinline__ void convert_q_body(const float* __restrict__ x,
                                               int8_t* __restrict__ xq,
                                               float* __restrict__ xsq,
                                               float* __restrict__ xscale,
                                               int nrows) {
    int warp = (blockIdx.x * blockDim.x + threadIdx.x) >> 5;
    int lane = threadIdx.x & 31;
    if (warp >= nrows) return;
    const float4* rp = reinterpret_cast<const float4*>(x + (size_t)warp * D_DIM);
    uint32_t* wp = reinterpret_cast<uint32_t*>(xq + (size_t)warp * D_DIM);

    float4 v[4];
    float s = 0.f, amax = 0.f;
#pragma unroll
    for (int i = 0; i < 4; i++) {
        v[i] = rp[lane + i * 32];
        s += v[i].x * v[i].x + v[i].y * v[i].y + v[i].z * v[i].z + v[i].w * v[i].w;
        amax = fmaxf(amax, fmaxf(fmaxf(fabsf(v[i].x), fabsf(v[i].y)),
                                 fmaxf(fabsf(v[i].z), fabsf(v[i].w))));
    }
#pragma unroll
    for (int o = 16; o > 0; o >>= 1) {
        s += __shfl_xor_sync(0xffffffffu, s, o);
        amax = fmaxf(amax, __shfl_xor_sync(0xffffffffu, amax, o));
    }
    amax = fmaxf(amax, 1e-30f);
    const float inv = 127.0f / amax;

#pragma unroll
    for (int i = 0; i < 4; i++) {
        int q0 = __float2int_rn(v[i].x * inv);
        int q1 = __float2int_rn(v[i].y * inv);
        int q2 = __float2int_rn(v[i].z * inv);
        int q3 = __float2int_rn(v[i].w * inv);
        uint32_t b = (q0 & 0xff) | ((q1 & 0xff) << 8) |
                     ((q2 & 0xff) << 16) | ((uint32_t)(q3 & 0xff) << 24);
        wp[lane + i * 32] = b;
    }
    if (lane == 0) {
        xsq[warp] = s;
        xscale[warp] = amax * (1.0f / 127.0f);
    }
}

__global__ void convert_e_kernel(const float* __restrict__ x) {
    convert_q_body(x, g_eq, g_xsq, g_xscale, N_ROWS);
}
__global__ void convert_p_kernel(const float* __restrict__ x) {
    convert_q_body(x, g_pq, g_psq, g_pscale, P_ROWS);
}

// ---------------- main GEMM + distance kernel -------------------------------
// 256 threads = 8 warps, warp grid 2x4, warp tile 64x32, CTA tile 128x128.
__global__ __launch_bounds__(256, 2) void gemm_mma_kernel(float* __restrict__ C) {
    extern __shared__ char smem[];
    const uint32_t sb = smem_u32(smem);

    const int tid  = threadIdx.x;
    const int wid  = tid >> 5;
    const int lane = tid & 31;
    const int wm = wid >> 2;   // 0..1   (64-row slab)
    const int wn = wid & 3;    // 0..3   (32-col slab)

    const int bRow = blockIdx.y * BM;
    const int bCol = blockIdx.x * BN;

    const char* gA = reinterpret_cast<const char*>(g_eq) + (size_t)bRow * D_DIM;
    const char* gB = reinterpret_cast<const char*>(g_pq) + (size_t)bCol * D_DIM;

    // cp.async: 2 threads per 64B row chunk -> 32B each.
    const int ldRow = tid >> 1;            // 0..127
    const int ldC   = (tid & 1) * 32;      // 0 or 32 bytes
    const size_t gOffBase = (size_t)ldRow * D_DIM + ldC;

    // ldmatrix lane addressing: row = lane&15, 16B chunk select = lane>>4
    const int lmRow   = lane & 15;
    const int lmChunk = (lane >> 4) << 4;

    int acc[4][4][4];
#pragma unroll
    for (int i = 0; i < 4; i++)
#pragma unroll
        for (int j = 0; j < 4; j++)
#pragma unroll
            for (int q = 0; q < 4; q++) acc[i][j][q] = 0;

    // ---- prologue ----
#pragma unroll
    for (int s = 0; s < STAGES - 1; s++) {
        uint32_t dstA = sb + s * STAGE_BYTES + ldRow * ROWB + ldC;
        const char* srcA = gA + gOffBase + s * BK;
        CP_ASYNC16(dstA, srcA);
        CP_ASYNC16(dstA + 16, srcA + 16);
        uint32_t dstB = dstA + TILE_BYTES;
        const char* srcB = gB + gOffBase + s * BK;
        CP_ASYNC16(dstB, srcB);
        CP_ASYNC16(dstB + 16, srcB + 16);
        CP_COMMIT();
    }

    // ---- mainloop ----
    for (int k = 0; k < K_ITERS; k++) {
        CP_WAIT(STAGES - 2);
        __syncthreads();

        {
            int kl = k + STAGES - 1;
            if (kl < K_ITERS) {
                int s = kl & (STAGES - 1);
                uint32_t dstA = sb + s * STAGE_BYTES + ldRow * ROWB + ldC;
                const char* srcA = gA + gOffBase + kl * BK;
                CP_ASYNC16(dstA, srcA);
                CP_ASYNC16(dstA + 16, srcA + 16);
                uint32_t dstB = dstA + TILE_BYTES;
                const char* srcB = gB + gOffBase + kl * BK;
                CP_ASYNC16(dstB, srcB);
                CP_ASYNC16(dstB + 16, srcB + 16);
            }
            CP_COMMIT();
        }

        const uint32_t stA = sb + (k & (STAGES - 1)) * STAGE_BYTES;
        const uint32_t stB = stA + TILE_BYTES;

#pragma unroll
        for (int kk = 0; kk < 2; kk++) {          // two k32 steps per 64B chunk
            const int kByte = kk * 32 + lmChunk;

            uint32_t a[4][4];
#pragma unroll
            for (int i = 0; i < 4; i++) {
                uint32_t addr = stA + (wm * 64 + i * 16 + lmRow) * ROWB + kByte;
                LDMATRIX_X4(a[i][0], a[i][1], a[i][2], a[i][3], addr);
            }
            uint32_t b[2][4];
#pragma unroll
            for (int jp = 0; jp < 2; jp++) {
                uint32_t addr = stB + (wn * 32 + jp * 16 + lmRow) * ROWB + kByte;
                LDMATRIX_X4(b[jp][0], b[jp][1], b[jp][2], b[jp][3], addr);
            }
#pragma unroll
            for (int i = 0; i < 4; i++) {
#pragma unroll
                for (int j = 0; j < 4; j++) {
                    int jp = j >> 1, h = j & 1;
                    MMA_16832_S8(acc[i][j][0], acc[i][j][1], acc[i][j][2], acc[i][j][3],
                                 a[i][0], a[i][1], a[i][2], a[i][3],
                                 b[jp][h], b[jp][2 + h]);
                }
            }
        }
    }

    // ---- epilogue: d = xs + ps - 2*sx*sp*acc ; out = -sqrt(max(d,0)) ----
    const int r0 = lane >> 2;        // 0..7
    const int cq = (lane & 3) * 2;   // 0,2,4,6

    float ps0[4], ps1[4], sp0[4], sp1[4];
#pragma unroll
    for (int j = 0; j < 4; j++) {
        int gc = bCol + wn * 32 + j * 8 + cq;
        ps0[j] = g_psq[gc];
        ps1[j] = g_psq[gc + 1];
        sp0[j] = g_pscale[gc];
        sp1[j] = g_pscale[gc + 1];
    }

#pragma unroll
    for (int i = 0; i < 4; i++) {
#pragma unroll
        for (int h = 0; h < 2; h++) {
            int grow = bRow + wm * 64 + i * 16 + r0 + h * 8;
            float xs = g_xsq[grow];
            float sx2 = -2.0f * g_xscale[grow];
            float* crow = C + (size_t)grow * P_ROWS + bCol + wn * 32;
#pragma unroll
            for (int j = 0; j < 4; j++) {
                float c0 = (float)acc[i][j][h * 2 + 0];
                float c1 = (float)acc[i][j][h * 2 + 1];
                float d0 = fmaf(sx2 * sp0[j], c0, xs + ps0[j]);
                float d1 = fmaf(sx2 * sp1[j], c1, xs + ps1[j]);
                float2 o;
                o.x = (d0 > 0.f) ? (-d0 * rsqrtf(d0)) : 0.f;
                o.y = (d1 > 0.f) ? (-d1 * rsqrtf(d1)) : 0.f;
                *reinterpret_cast<float2*>(crow + j * 8 + cq) = o;
            }
        }
    }
}

// ---------------- launch ----------------------------------------------------
extern "C" void kernel_launch(void* const* d_in, const int* in_sizes, int n_in,
                              void* d_out, int out_size) {
    const float* emb   = (const float*)d_in[0];  // [N, D]
    const float* proto = (const float*)d_in[1];  // [P, D]
    float* out = (float*)d_out;                  // [N, P]

    cudaFuncSetAttribute(gemm_mma_kernel,
                         cudaFuncAttributeMaxDynamicSharedMemorySize, SMEM_TOTAL);

    convert_e_kernel<<<N_ROWS / 8, 256>>>(emb);
    convert_p_kernel<<<P_ROWS / 8, 256>>>(proto);

    dim3 grid(P_ROWS / BN, N_ROWS / BM);  // (16, 512): columns fastest -> A reuse in L2
    gemm_mma_kernel<<<grid, 256, SMEM_TOTAL>>>(out);
}

// round 10
// speedup vs baseline: 1.2473x; 1.2473x over previous
#include <cuda_runtime.h>
#include <cuda_bf16.h>
#include <stdint.h>
#include <math.h>

#define N_ROWS 65536
#define P_ROWS 2048
#define D_DIM  512

#define BM 64
#define BN 128
#define BK 32            // bf16 elements -> 64 bytes per row-chunk
#define STAGES 3
#define K_ITERS (D_DIM / BK)   // 16

// smem: padded 80B row stride (conflict-free ldmatrix, 16B-aligned cp.async)
#define ROWB 80
#define A_TILE_BYTES (BM * ROWB)            // 5120
#define B_TILE_BYTES (BN * ROWB)            // 10240
#define STAGE_BYTES (A_TILE_BYTES + B_TILE_BYTES)  // 15360
#define SMEM_TOTAL (STAGES * STAGE_BYTES)   // 46080 -> 4 CTAs/SM

// ---------------- scratch (static device globals; no runtime allocation) ----
__device__ float g_xsq[N_ROWS];
__device__ float g_psq[P_ROWS];
__device__ __nv_bfloat16 g_ebf[(size_t)N_ROWS * D_DIM];
__device__ __nv_bfloat16 g_pbf[(size_t)P_ROWS * D_DIM];

// ---------------- PTX helpers ----------------------------------------------
__device__ __forceinline__ uint32_t smem_u32(const void* p) {
    uint32_t a;
    asm("{ .reg .u64 t; cvta.to.shared.u64 t, %1; cvt.u32.u64 %0, t; }" : "=r"(a) : "l"(p));
    return a;
}

#define CP_ASYNC16(dst, src) \
    asm volatile("cp.async.cg.shared.global [%0], [%1], 16;" :: "r"(dst), "l"(src) : "memory")
#define CP_COMMIT() asm volatile("cp.async.commit_group;" ::: "memory")
#define CP_WAIT(n)  asm volatile("cp.async.wait_group %0;" :: "n"(n) : "memory")

#define LDMATRIX_X4(r0, r1, r2, r3, addr) \
    asm volatile("ldmatrix.sync.aligned.m8n8.x4.shared.b16 {%0,%1,%2,%3}, [%4];" \
        : "=r"(r0), "=r"(r1), "=r"(r2), "=r"(r3) : "r"(addr))

#define MMA_16816_BF16(c0, c1, c2, c3, a0, a1, a2, a3, b0, b1) \
    asm volatile("mma.sync.aligned.m16n8k16.row.col.f32.bf16.bf16.f32 " \
        "{%0,%1,%2,%3}, {%4,%5,%6,%7}, {%8,%9}, {%0,%1,%2,%3};" \
        : "+f"(c0), "+f"(c1), "+f"(c2), "+f"(c3) \
        : "r"(a0), "r"(a1), "r"(a2), "r"(a3), "r"(b0), "r"(b1))

// ---------------- convert fp32 -> bf16 + row norms (fused e + p) ------------
__global__ void convert_all_kernel(const float* __restrict__ e,
                                   const float* __restrict__ p) {
    int warp = (blockIdx.x * blockDim.x + threadIdx.x) >> 5;
    int lane = threadIdx.x & 31;

    const float* src;
    __nv_bfloat16* dst;
    float* sq;
    int row;
    if (warp < N_ROWS) {
        src = e; dst = g_ebf; sq = g_xsq; row = warp;
    } else if (warp < N_ROWS + P_ROWS) {
        src = p; dst = g_pbf; sq = g_psq; row = warp - N_ROWS;
    } else return;

    const float4* rp = reinterpret_cast<const float4*>(src + (size_t)row * D_DIM);
    uint2* wp = reinterpret_cast<uint2*>(dst + (size_t)row * D_DIM);
    float s = 0.f;
#pragma unroll
    for (int i = 0; i < 4; i++) {
        float4 v = rp[lane + i * 32];
        s += v.x * v.x + v.y * v.y + v.z * v.z + v.w * v.w;
        __nv_bfloat162 lo = __floats2bfloat162_rn(v.x, v.y);
        __nv_bfloat162 hi = __floats2bfloat162_rn(v.z, v.w);
        uint2 u;
        u.x = *reinterpret_cast<uint32_t*>(&lo);
        u.y = *reinterpret_cast<uint32_t*>(&hi);
        wp[lane + i * 32] = u;
    }
#pragma unroll
    for (int o = 16; o > 0; o >>= 1) s += __shfl_xor_sync(0xffffffffu, s, o);
    if (lane == 0) sq[row] = s;
}

// ---------------- main GEMM + distance kernel -------------------------------
// 128 threads = 4 warps, warp grid 1x4, warp tile 64x32, CTA tile 64x128.
__global__ __launch_bounds__(128, 4) void gemm_mma_kernel(float* __restrict__ C) {
    extern __shared__ char smem[];
    const uint32_t sb = smem_u32(smem);

    const int tid  = threadIdx.x;
    const int wid  = tid >> 5;
    const int lane = tid & 31;
    const int wn = wid;        // 0..3 (32-col slab); all warps span the full 64 rows

    const int bRow = blockIdx.y * BM;
    const int bCol = blockIdx.x * BN;

    const char* gA = reinterpret_cast<const char*>(g_ebf) + (size_t)bRow * (D_DIM * 2);
    const char* gB = reinterpret_cast<const char*>(g_pbf) + (size_t)bCol * (D_DIM * 2);

    // cp.async per stage: A 64 rows x 64B (2 thr/row, 32B each);
    //                     B 128 rows x 64B (1 thr/row, 64B each).
    const int aRow = tid >> 1;
    const int aCol = (tid & 1) * 32;
    const size_t gAoff = (size_t)aRow * (D_DIM * 2) + aCol;
    const uint32_t sAoff = aRow * ROWB + aCol;
    const size_t gBoff = (size_t)tid * (D_DIM * 2);
    const uint32_t sBoff = tid * ROWB;

    // ldmatrix lane addressing
    const int lmRow   = lane & 15;
    const int lmChunk = (lane >> 4) << 4;

    float acc[4][4][4];
#pragma unroll
    for (int i = 0; i < 4; i++)
#pragma unroll
        for (int j = 0; j < 4; j++)
#pragma unroll
            for (int q = 0; q < 4; q++) acc[i][j][q] = 0.f;

    // ---- prologue: fill STAGES-1 = 2 stages ----
#pragma unroll
    for (int s = 0; s < STAGES - 1; s++) {
        uint32_t stg = sb + s * STAGE_BYTES;
        const char* srcA = gA + gAoff + s * (BK * 2);
        CP_ASYNC16(stg + sAoff, srcA);
        CP_ASYNC16(stg + sAoff + 16, srcA + 16);
        const char* srcB = gB + gBoff + s * (BK * 2);
        uint32_t dstB = stg + A_TILE_BYTES + sBoff;
#pragma unroll
        for (int c = 0; c < 64; c += 16) CP_ASYNC16(dstB + c, srcB + c);
        CP_COMMIT();
    }

    // ---- mainloop ----
    int sc = 0;                        // compute stage
    int sl = STAGES - 1;               // load stage
    for (int k = 0; k < K_ITERS; k++) {
        CP_WAIT(STAGES - 2);
        __syncthreads();

        {
            int kl = k + STAGES - 1;
            if (kl < K_ITERS) {
                uint32_t stg = sb + sl * STAGE_BYTES;
                const char* srcA = gA + gAoff + kl * (BK * 2);
                CP_ASYNC16(stg + sAoff, srcA);
                CP_ASYNC16(stg + sAoff + 16, srcA + 16);
                const char* srcB = gB + gBoff + kl * (BK * 2);
                uint32_t dstB = stg + A_TILE_BYTES + sBoff;
#pragma unroll
                for (int c = 0; c < 64; c += 16) CP_ASYNC16(dstB + c, srcB + c);
            }
            CP_COMMIT();
            if (++sl == STAGES) sl = 0;
        }

        const uint32_t stA = sb + sc * STAGE_BYTES;
        const uint32_t stB = stA + A_TILE_BYTES;
        if (++sc == STAGES) sc = 0;

#pragma unroll
        for (int kk = 0; kk < 2; kk++) {
            const int kByte = kk * 32 + lmChunk;

            uint32_t a[4][4];
#pragma unroll
            for (int i = 0; i < 4; i++) {
                uint32_t addr = stA + (i * 16 + lmRow) * ROWB + kByte;
                LDMATRIX_X4(a[i][0], a[i][1], a[i][2], a[i][3], addr);
            }
            uint32_t b[2][4];
#pragma unroll
            for (int jp = 0; jp < 2; jp++) {
                uint32_t addr = stB + (wn * 32 + jp * 16 + lmRow) * ROWB + kByte;
                LDMATRIX_X4(b[jp][0], b[jp][1], b[jp][2], b[jp][3], addr);
            }
#pragma unroll
            for (int i = 0; i < 4; i++) {
#pragma unroll
                for (int j = 0; j < 4; j++) {
                    int jp = j >> 1, h = j & 1;
                    MMA_16816_BF16(acc[i][j][0], acc[i][j][1], acc[i][j][2], acc[i][j][3],
                                   a[i][0], a[i][1], a[i][2], a[i][3],
                                   b[jp][h], b[jp][2 + h]);
                }
            }
        }
    }

    // ---- epilogue: d = xs + ps - 2*cross ; out = -sqrt(max(d,0)) ----
    const int r0 = lane >> 2;        // 0..7
    const int cq = (lane & 3) * 2;   // 0,2,4,6

    float ps0[4], ps1[4];
#pragma unroll
    for (int j = 0; j < 4; j++) {
        int gc = bCol + wn * 32 + j * 8 + cq;
        ps0[j] = g_psq[gc];
        ps1[j] = g_psq[gc + 1];
    }

#pragma unroll
    for (int i = 0; i < 4; i++) {
#pragma unroll
        for (int h = 0; h < 2; h++) {
            int grow = bRow + i * 16 + r0 + h * 8;
            float xs = g_xsq[grow];
            float* crow = C + (size_t)grow * P_ROWS + bCol + wn * 32;
#pragma unroll
            for (int j = 0; j < 4; j++) {
                float c0 = acc[i][j][h * 2 + 0];
                float c1 = acc[i][j][h * 2 + 1];
                float d0 = fmaf(-2.f, c0, xs + ps0[j]);
                float d1 = fmaf(-2.f, c1, xs + ps1[j]);
                float2 o;
                o.x = (d0 > 0.f) ? (-d0 * rsqrtf(d0)) : 0.f;
                o.y = (d1 > 0.f) ? (-d1 * rsqrtf(d1)) : 0.f;
                *reinterpret_cast<float2*>(crow + j * 8 + cq) = o;
            }
        }
    }
}

// ---------------- launch ----------------------------------------------------
extern "C" void kernel_launch(void* const* d_in, const int* in_sizes, int n_in,
                              void* d_out, int out_size) {
    const float* emb   = (const float*)d_in[0];  // [N, D]
    const float* proto = (const float*)d_in[1];  // [P, D]
    float* out = (float*)d_out;                  // [N, P]

    cudaFuncSetAttribute(gemm_mma_kernel,
                         cudaFuncAttributeMaxDynamicSharedMemorySize, SMEM_TOTAL);

    convert_all_kernel<<<(N_ROWS + P_ROWS) / 8, 256>>>(emb, proto);

    dim3 grid(P_ROWS / BN, N_ROWS / BM);  // (16, 1024): columns fastest -> A reuse in L2
    gemm_mma_kernel<<<grid, 128, SMEM_TOTAL>>>(out);
}

// round 12
// speedup vs baseline: 2.4589x; 1.9714x over previous
#include <cuda_runtime.h>
#include <cuda_bf16.h>
#include <stdint.h>
#include <math.h>

#define N_ROWS 65536
#define P_ROWS 2048
#define D_DIM  512

#define BM 128
#define BN 128
#define STAGES 4
#define K_CHUNKS 16            // 32 bf16 (64B) per row per chunk
#define CHUNK_BYTES 8192       // 128 rows x 64B, contiguous + pre-swizzled in gmem
#define STAGE_BYTES 16384      // A chunk + B chunk
#define SM_BAR 65536           // after 4 stages
#define SMEM_TOTAL (65536 + 128)

// ---------------- scratch (static device globals; no runtime allocation) ----
__device__ float g_xsq[N_ROWS];
__device__ float g_psq[P_ROWS];
// tiled+swizzled bf16 images: [tile][kc][128 x 64B], byte-addressed
__device__ unsigned char g_ebf[(size_t)N_ROWS * D_DIM * 2];
__device__ unsigned char g_pbf[(size_t)P_ROWS * D_DIM * 2];

// ---------------- PTX helpers ----------------------------------------------
__device__ __forceinline__ uint32_t smem_u32(const void* p) {
    uint32_t a;
    asm("{ .reg .u64 t; cvta.to.shared.u64 t, %1; cvt.u32.u64 %0, t; }" : "=r"(a) : "l"(p));
    return a;
}

#define MBARRIER_INIT(addr, cnt) \
    asm volatile("mbarrier.init.shared.b64 [%0], %1;" :: "r"((uint32_t)(addr)), "r"((uint32_t)(cnt)) : "memory")
#define MBARRIER_ARRIVE(addr) \
    asm volatile("mbarrier.arrive.shared.b64 _, [%0];" :: "r"((uint32_t)(addr)) : "memory")
#define MBARRIER_EXPECT_TX(addr, bytes) \
    asm volatile("mbarrier.arrive.expect_tx.shared.b64 _, [%0], %1;" :: "r"((uint32_t)(addr)), "r"((uint32_t)(bytes)) : "memory")

#define MBARRIER_WAIT_PARITY(mbar_smem_addr, phase_parity) do { \
    uint32_t _mbar = (uint32_t)(mbar_smem_addr); \
    uint32_t _parity = (uint32_t)(phase_parity); \
    uint32_t _done; \
    asm volatile( \
        "{\n\t.reg .pred p;\n\t" \
        "mbarrier.try_wait.parity.acquire.cta.shared::cta.b64 p, [%1], %2;\n\t" \
        "selp.b32 %0, 1, 0, p;\n\t}" \
        : "=r"(_done) : "r"(_mbar), "r"(_parity) : "memory"); \
    if (!_done) { \
        asm volatile( \
            "{\n\t.reg .pred P1;\n\t" \
            "WAIT_LOOP_%=:\n\t" \
            "mbarrier.try_wait.parity.acquire.cta.shared::cta.b64 P1, [%0], %1, 0x989680;\n\t" \
            "@P1 bra.uni WAIT_DONE_%=;\n\t" \
            "bra.uni WAIT_LOOP_%=;\n\t" \
            "WAIT_DONE_%=:\n\t}" \
            :: "r"(_mbar), "r"(_parity) : "memory"); \
    } \
} while(0)

// one-shot 8KB bulk copy gmem -> smem, completion via mbarrier tx bytes
#define CP_BULK8K(dst_smem, src_gmem, mbar) \
    asm volatile("{\n\t.reg .u64 g;\n\tcvta.to.global.u64 g, %1;\n\t" \
        "cp.async.bulk.shared::cluster.global.mbarrier::complete_tx::bytes [%0], [g], %2, [%3];\n\t}" \
        :: "r"((uint32_t)(dst_smem)), "l"(src_gmem), "n"(8192), "r"((uint32_t)(mbar)) : "memory")

#define LDMATRIX_X4(r0, r1, r2, r3, addr) \
    asm volatile("ldmatrix.sync.aligned.m8n8.x4.shared.b16 {%0,%1,%2,%3}, [%4];" \
        : "=r"(r0), "=r"(r1), "=r"(r2), "=r"(r3) : "r"(addr))

#define MMA_16816_BF16(c0, c1, c2, c3, a0, a1, a2, a3, b0, b1) \
    asm volatile("mma.sync.aligned.m16n8k16.row.col.f32.bf16.bf16.f32 " \
        "{%0,%1,%2,%3}, {%4,%5,%6,%7}, {%8,%9}, {%0,%1,%2,%3};" \
        : "+f"(c0), "+f"(c1), "+f"(c2), "+f"(c3) \
        : "r"(a0), "r"(a1), "r"(a2), "r"(a3), "r"(b0), "r"(b1))

// ---------------- convert fp32 -> bf16 tiled+swizzled + row norms -----------
// One warp per row. Row's 512 elements -> 16 k-chunks of 64B; element unit u
// (16B, u=0..63): kc=u>>2, c=u&3; stored at tile_base + kc*8192 + r*64 +
// ((c ^ ((r>>1)&3)) << 4). Lane handles units 2*lane, 2*lane+1.
__global__ void convert_all_kernel(const float* __restrict__ e,
                                   const float* __restrict__ p) {
    int warp = (blockIdx.x * blockDim.x + threadIdx.x) >> 5;
    int lane = threadIdx.x & 31;

    const float* src;
    unsigned char* dstbase;
    float* sq;
    int row;
    if (warp < N_ROWS) {
        src = e; dstbase = g_ebf; sq = g_xsq; row = warp;
    } else if (warp < N_ROWS + P_ROWS) {
        src = p; dstbase = g_pbf; sq = g_psq; row = warp - N_ROWS;
    } else return;

    const int t = row >> 7;
    const int r = row & 127;
    const float4* rp = reinterpret_cast<const float4*>(src + (size_t)row * D_DIM);

    float s = 0.f;
    uint4 un[2];
#pragma unroll
    for (int hu = 0; hu < 2; hu++) {
        uint32_t w[4];
#pragma unroll
        for (int j = 0; j < 2; j++) {
            float4 v = rp[lane * 4 + hu * 2 + j];
            s += v.x * v.x + v.y * v.y + v.z * v.z + v.w * v.w;
            __nv_bfloat162 lo = __floats2bfloat162_rn(v.x, v.y);
            __nv_bfloat162 hi = __floats2bfloat162_rn(v.z, v.w);
            w[j * 2 + 0] = *reinterpret_cast<uint32_t*>(&lo);
            w[j * 2 + 1] = *reinterpret_cast<uint32_t*>(&hi);
        }
        un[hu] = make_uint4(w[0], w[1], w[2], w[3]);
    }
#pragma unroll
    for (int o = 16; o > 0; o >>= 1) s += __shfl_xor_sync(0xffffffffu, s, o);
    if (lane == 0) sq[row] = s;

    unsigned char* tb = dstbase + (size_t)t * (K_CHUNKS * CHUNK_BYTES);
#pragma unroll
    for (int hu = 0; hu < 2; hu++) {
        int u = lane * 2 + hu;
        int kc = u >> 2, c = u & 3;
        size_t off = (size_t)kc * CHUNK_BYTES + r * 64 + (((c ^ ((r >> 1) & 3))) << 4);
        *reinterpret_cast<uint4*>(tb + off) = un[hu];
    }
}

// ---------------- main GEMM + distance kernel -------------------------------
// 256 threads, warp grid 2x4 (warp tile 64x32), CTA tile 128x128, 4-stage
// bulk-copy ring fed by thread 0, mbarrier full/empty handshake.
__global__ __launch_bounds__(256, 2) void gemm_mma_kernel(float* __restrict__ C) {
    extern __shared__ char smem[];
    const uint32_t sb = smem_u32(smem);

    const int tid  = threadIdx.x;
    const int wid  = tid >> 5;
    const int lane = tid & 31;
    const int wm = wid >> 2;   // 0..1
    const int wn = wid & 3;    // 0..3

    const int mt = blockIdx.y;            // m-tile (128 rows)
    const int pt = blockIdx.x;            // p-tile (128 cols)
    const int bRow = mt * BM;
    const int bCol = pt * BN;

    const unsigned char* gAt = g_ebf + (size_t)mt * (K_CHUNKS * CHUNK_BYTES);
    const unsigned char* gBt = g_pbf + (size_t)pt * (K_CHUNKS * CHUNK_BYTES);

    const uint32_t fullb  = sb + SM_BAR;        // 4 x 8B
    const uint32_t emptyb = sb + SM_BAR + 64;   // 4 x 8B

    if (tid == 0) {
#pragma unroll
        for (int s = 0; s < STAGES; s++) {
            MBARRIER_INIT(fullb + s * 8, 1);    // tx-based (expect_tx arrive)
            MBARRIER_INIT(emptyb + s * 8, 8);   // one arrive per warp
        }
    }
    __syncthreads();

    // prologue: issue stages 0..2
    if (tid == 0) {
#pragma unroll
        for (int s = 0; s < STAGES - 1; s++) {
            MBARRIER_EXPECT_TX(fullb + s * 8, STAGE_BYTES);
            CP_BULK8K(sb + s * STAGE_BYTES, gAt + (size_t)s * CHUNK_BYTES, fullb + s * 8);
            CP_BULK8K(sb + s * STAGE_BYTES + CHUNK_BYTES, gBt + (size_t)s * CHUNK_BYTES, fullb + s * 8);
        }
    }

    // loop-invariant ldmatrix addressing: addr = stage + rowOff + (kByte ^ sx)
    const int lmRow   = lane & 15;
    const int lmChunk = (lane >> 4) << 4;
    uint32_t aOff[4], sxA[4];
#pragma unroll
    for (int i = 0; i < 4; i++) {
        int r = wm * 64 + i * 16 + lmRow;
        aOff[i] = r * 64;
        sxA[i] = ((r >> 1) & 3) << 4;
    }
    uint32_t bOff[2], sxB[2];
#pragma unroll
    for (int jp = 0; jp < 2; jp++) {
        int r = wn * 32 + jp * 16 + lmRow;
        bOff[jp] = r * 64;
        sxB[jp] = ((r >> 1) & 3) << 4;
    }

    float acc[4][4][4];
#pragma unroll
    for (int i = 0; i < 4; i++)
#pragma unroll
        for (int j = 0; j < 4; j++)
#pragma unroll
            for (int q = 0; q < 4; q++) acc[i][j][q] = 0.f;

#pragma unroll 4
    for (int k = 0; k < K_CHUNKS; k++) {
        // producer: refill stage k+3
        if (tid == 0) {
            int kl = k + STAGES - 1;
            if (kl < K_CHUNKS) {
                int ls = kl & 3;
                if (kl >= STAGES)
                    MBARRIER_WAIT_PARITY(emptyb + ls * 8, ((kl >> 2) & 1) ^ 1);
                MBARRIER_EXPECT_TX(fullb + ls * 8, STAGE_BYTES);
                CP_BULK8K(sb + ls * STAGE_BYTES, gAt + (size_t)kl * CHUNK_BYTES, fullb + ls * 8);
                CP_BULK8K(sb + ls * STAGE_BYTES + CHUNK_BYTES, gBt + (size_t)kl * CHUNK_BYTES, fullb + ls * 8);
            }
        }

        const int slot = k & 3;
        MBARRIER_WAIT_PARITY(fullb + slot * 8, (k >> 2) & 1);

        const uint32_t stA = sb + slot * STAGE_BYTES;
        const uint32_t stB = stA + CHUNK_BYTES;

#pragma unroll
        for (int kk = 0; kk < 2; kk++) {
            const uint32_t kByte = kk * 32 + lmChunk;

            uint32_t a[4][4];
#pragma unroll
            for (int i = 0; i < 4; i++) {
                uint32_t addr = stA + aOff[i] + (kByte ^ sxA[i]);
                LDMATRIX_X4(a[i][0], a[i][1], a[i][2], a[i][3], addr);
            }
            uint32_t b[2][4];
#pragma unroll
            for (int jp = 0; jp < 2; jp++) {
                uint32_t addr = stB + bOff[jp] + (kByte ^ sxB[jp]);
                LDMATRIX_X4(b[jp][0], b[jp][1], b[jp][2], b[jp][3], addr);
            }
#pragma unroll
            for (int i = 0; i < 4; i++) {
#pragma unroll
                for (int j = 0; j < 4; j++) {
                    int jp = j >> 1, h = j & 1;
                    MMA_16816_BF16(acc[i][j][0], acc[i][j][1], acc[i][j][2], acc[i][j][3],
                                   a[i][0], a[i][1], a[i][2], a[i][3],
                                   b[jp][h], b[jp][2 + h]);
                }
            }
        }
        if (lane == 0) MBARRIER_ARRIVE(emptyb + slot * 8);
    }

    // ---- epilogue: d = xs + ps - 2*cross ; out = -sqrt(max(d,0)) ----
    const int r0 = lane >> 2;        // 0..7
    const int cq = (lane & 3) * 2;   // 0,2,4,6

    float ps0[4], ps1[4];
#pragma unroll
    for (int j = 0; j < 4; j++) {
        int gc = bCol + wn * 32 + j * 8 + cq;
        ps0[j] = g_psq[gc];
        ps1[j] = g_psq[gc + 1];
    }

#pragma unroll
    for (int i = 0; i < 4; i++) {
#pragma unroll
        for (int h = 0; h < 2; h++) {
            int grow = bRow + wm * 64 + i * 16 + r0 + h * 8;
            float xs = g_xsq[grow];
            float* crow = C + (size_t)grow * P_ROWS + bCol + wn * 32;
#pragma unroll
            for (int j = 0; j < 4; j++) {
                float c0 = acc[i][j][h * 2 + 0];
                float c1 = acc[i][j][h * 2 + 1];
                float d0 = fmaf(-2.f, c0, xs + ps0[j]);
                float d1 = fmaf(-2.f, c1, xs + ps1[j]);
                float2 o;
                o.x = (d0 > 0.f) ? (-d0 * rsqrtf(d0)) : 0.f;
                o.y = (d1 > 0.f) ? (-d1 * rsqrtf(d1)) : 0.f;
                *reinterpret_cast<float2*>(crow + j * 8 + cq) = o;
            }
        }
    }
}

// ---------------- launch ----------------------------------------------------
extern "C" void kernel_launch(void* const* d_in, const int* in_sizes, int n_in,
                              void* d_out, int out_size) {
    const float* emb   = (const float*)d_in[0];  // [N, D]
    const float* proto = (const float*)d_in[1];  // [P, D]
    float* out = (float*)d_out;                  // [N, P]

    cudaFuncSetAttribute(gemm_mma_kernel,
                         cudaFuncAttributeMaxDynamicSharedMemorySize, SMEM_TOTAL);

    convert_all_kernel<<<(N_ROWS + P_ROWS) / 8, 256>>>(emb, proto);

    dim3 grid(P_ROWS / BN, N_ROWS / BM);  // (16, 512): columns fastest -> A reuse in L2
    gemm_mma_kernel<<<grid, 256, SMEM_TOTAL>>>(out);
}

// round 14
// speedup vs baseline: 2.5494x; 1.0368x over previous
#include <cuda_runtime.h>
#include <cuda_bf16.h>
#include <stdint.h>
#include <math.h>

#define N_ROWS 65536
#define P_ROWS 2048
#define D_DIM  512

#define BM 128
#define BN 128
#define STAGES 3
#define K_CHUNKS 8             // 64 bf16 (128B) per row per chunk
#define CHUNK_BYTES 16384      // 128 rows x 128B, contiguous + pre-swizzled in gmem
#define STAGE_BYTES 32768      // A chunk + B chunk
#define SM_BAR (STAGES * STAGE_BYTES)      // 98304
#define SMEM_TOTAL (SM_BAR + 128)

// ---------------- scratch (static device globals; no runtime allocation) ----
__device__ float g_xsq[N_ROWS];
__device__ float g_psq[P_ROWS];
// tiled+swizzled bf16 images: [tile][kc][128 x 128B], byte-addressed
__device__ unsigned char g_ebf[(size_t)N_ROWS * D_DIM * 2];
__device__ unsigned char g_pbf[(size_t)P_ROWS * D_DIM * 2];

// ---------------- PTX helpers ----------------------------------------------
__device__ __forceinline__ uint32_t smem_u32(const void* p) {
    uint32_t a;
    asm("{ .reg .u64 t; cvta.to.shared.u64 t, %1; cvt.u32.u64 %0, t; }" : "=r"(a) : "l"(p));
    return a;
}

#define MBARRIER_INIT(addr, cnt) \
    asm volatile("mbarrier.init.shared.b64 [%0], %1;" :: "r"((uint32_t)(addr)), "r"((uint32_t)(cnt)) : "memory")
#define MBARRIER_ARRIVE(addr) \
    asm volatile("mbarrier.arrive.shared.b64 _, [%0];" :: "r"((uint32_t)(addr)) : "memory")
#define MBARRIER_EXPECT_TX(addr, bytes) \
    asm volatile("mbarrier.arrive.expect_tx.shared.b64 _, [%0], %1;" :: "r"((uint32_t)(addr)), "r"((uint32_t)(bytes)) : "memory")

#define MBARRIER_WAIT_PARITY(mbar_smem_addr, phase_parity) do { \
    uint32_t _mbar = (uint32_t)(mbar_smem_addr); \
    uint32_t _parity = (uint32_t)(phase_parity); \
    uint32_t _done; \
    asm volatile( \
        "{\n\t.reg .pred p;\n\t" \
        "mbarrier.try_wait.parity.acquire.cta.shared::cta.b64 p, [%1], %2;\n\t" \
        "selp.b32 %0, 1, 0, p;\n\t}" \
        : "=r"(_done) : "r"(_mbar), "r"(_parity) : "memory"); \
    if (!_done) { \
        asm volatile( \
            "{\n\t.reg .pred P1;\n\t" \
            "WAIT_LOOP_%=:\n\t" \
            "mbarrier.try_wait.parity.acquire.cta.shared::cta.b64 P1, [%0], %1, 0x989680;\n\t" \
            "@P1 bra.uni WAIT_DONE_%=;\n\t" \
            "bra.uni WAIT_LOOP_%=;\n\t" \
            "WAIT_DONE_%=:\n\t}" \
            :: "r"(_mbar), "r"(_parity) : "memory"); \
    } \
} while(0)

// one-shot 16KB bulk copy gmem -> smem, completion via mbarrier tx bytes
#define CP_BULK16K(dst_smem, src_gmem, mbar) \
    asm volatile("{\n\t.reg .u64 g;\n\tcvta.to.global.u64 g, %1;\n\t" \
        "cp.async.bulk.shared::cluster.global.mbarrier::complete_tx::bytes [%0], [g], %2, [%3];\n\t}" \
        :: "r"((uint32_t)(dst_smem)), "l"(src_gmem), "n"(16384), "r"((uint32_t)(mbar)) : "memory")

#define LDMATRIX_X4(r0, r1, r2, r3, addr) \
    asm volatile("ldmatrix.sync.aligned.m8n8.x4.shared.b16 {%0,%1,%2,%3}, [%4];" \
        : "=r"(r0), "=r"(r1), "=r"(r2), "=r"(r3) : "r"(addr))

#define MMA_16816_BF16(c0, c1, c2, c3, a0, a1, a2, a3, b0, b1) \
    asm volatile("mma.sync.aligned.m16n8k16.row.col.f32.bf16.bf16.f32 " \
        "{%0,%1,%2,%3}, {%4,%5,%6,%7}, {%8,%9}, {%0,%1,%2,%3};" \
        : "+f"(c0), "+f"(c1), "+f"(c2), "+f"(c3) \
        : "r"(a0), "r"(a1), "r"(a2), "r"(a3), "r"(b0), "r"(b1))

// ---------------- convert fp32 -> bf16 tiled+swizzled + row norms -----------
// One warp per row. Row's 512 bf16 = 64 16B-units; kc = u>>3 (8 chunks of
// 128B/row), c = u&7; stored at tile_base + kc*16384 + r*128 + ((c^(r&7))<<4).
__global__ void convert_all_kernel(const float* __restrict__ e,
                                   const float* __restrict__ p) {
    int warp = (blockIdx.x * blockDim.x + threadIdx.x) >> 5;
    int lane = threadIdx.x & 31;

    const float* src;
    unsigned char* dstbase;
    float* sq;
    int row;
    if (warp < N_ROWS) {
        src = e; dstbase = g_ebf; sq = g_xsq; row = warp;
    } else if (warp < N_ROWS + P_ROWS) {
        src = p; dstbase = g_pbf; sq = g_psq; row = warp - N_ROWS;
    } else return;

    const int t = row >> 7;
    const int r = row & 127;
    const float4* rp = reinterpret_cast<const float4*>(src + (size_t)row * D_DIM);

    float s = 0.f;
    uint4 un[2];
#pragma unroll
    for (int hu = 0; hu < 2; hu++) {
        uint32_t w[4];
#pragma unroll
        for (int j = 0; j < 2; j++) {
            float4 v = rp[lane * 4 + hu * 2 + j];
            s += v.x * v.x + v.y * v.y + v.z * v.z + v.w * v.w;
            __nv_bfloat162 lo = __floats2bfloat162_rn(v.x, v.y);
            __nv_bfloat162 hi = __floats2bfloat162_rn(v.z, v.w);
            w[j * 2 + 0] = *reinterpret_cast<uint32_t*>(&lo);
            w[j * 2 + 1] = *reinterpret_cast<uint32_t*>(&hi);
        }
        un[hu] = make_uint4(w[0], w[1], w[2], w[3]);
    }
#pragma unroll
    for (int o = 16; o > 0; o >>= 1) s += __shfl_xor_sync(0xffffffffu, s, o);
    if (lane == 0) sq[row] = s;

    unsigned char* tb = dstbase + (size_t)t * (K_CHUNKS * CHUNK_BYTES);
#pragma unroll
    for (int hu = 0; hu < 2; hu++) {
        int u = lane * 2 + hu;
        int kc = u >> 3, c = u & 7;
        size_t off = (size_t)kc * CHUNK_BYTES + r * 128 + (((c ^ (r & 7))) << 4);
        *reinterpret_cast<uint4*>(tb + off) = un[hu];
    }
}

// ---------------- main GEMM + distance kernel -------------------------------
// 256 threads, warp grid 2x4 (warp tile 64x32), CTA tile 128x128, 3-stage
// 16KB bulk-copy ring fed by thread 0, mbarrier full/empty handshake.
__global__ __launch_bounds__(256, 2) void gemm_mma_kernel(float* __restrict__ C) {
    extern __shared__ char smem[];
    const uint32_t sb = smem_u32(smem);

    const int tid  = threadIdx.x;
    const int wid  = tid >> 5;
    const int lane = tid & 31;
    const int wm = wid >> 2;   // 0..1
    const int wn = wid & 3;    // 0..3

    const int mt = blockIdx.y;            // m-tile (128 rows)
    const int pt = blockIdx.x;            // p-tile (128 cols)
    const int bRow = mt * BM;
    const int bCol = pt * BN;

    const unsigned char* gAt = g_ebf + (size_t)mt * (K_CHUNKS * CHUNK_BYTES);
    const unsigned char* gBt = g_pbf + (size_t)pt * (K_CHUNKS * CHUNK_BYTES);

    const uint32_t fullb  = sb + SM_BAR;        // 3 x 8B
    const uint32_t emptyb = sb + SM_BAR + 64;   // 3 x 8B

    if (tid == 0) {
#pragma unroll
        for (int s = 0; s < STAGES; s++) {
            MBARRIER_INIT(fullb + s * 8, 1);    // tx-based (expect_tx arrive)
            MBARRIER_INIT(emptyb + s * 8, 8);   // one arrive per warp
        }
    }
    __syncthreads();

    // prologue: issue stages 0..1
    if (tid == 0) {
#pragma unroll
        for (int s = 0; s < STAGES - 1; s++) {
            MBARRIER_EXPECT_TX(fullb + s * 8, STAGE_BYTES);
            CP_BULK16K(sb + s * STAGE_BYTES, gAt + (size_t)s * CHUNK_BYTES, fullb + s * 8);
            CP_BULK16K(sb + s * STAGE_BYTES + CHUNK_BYTES, gBt + (size_t)s * CHUNK_BYTES, fullb + s * 8);
        }
    }

    // loop-invariant ldmatrix addressing: addr = stage + rowOff + ((kU^sx)<<4)
    const int lmRow = lane & 15;
    const int lmHi  = lane >> 4;            // 16B-unit select within k16 step
    uint32_t aOff[4], sxA[4];
#pragma unroll
    for (int i = 0; i < 4; i++) {
        int r = wm * 64 + i * 16 + lmRow;
        aOff[i] = r * 128;
        sxA[i] = r & 7;
    }
    uint32_t bOff[2], sxB[2];
#pragma unroll
    for (int jp = 0; jp < 2; jp++) {
        int r = wn * 32 + jp * 16 + lmRow;
        bOff[jp] = r * 128;
        sxB[jp] = r & 7;
    }

    float acc[4][4][4];
#pragma unroll
    for (int i = 0; i < 4; i++)
#pragma unroll
        for (int j = 0; j < 4; j++)
#pragma unroll
            for (int q = 0; q < 4; q++) acc[i][j][q] = 0.f;

#pragma unroll
    for (int k = 0; k < K_CHUNKS; k++) {
        // producer: refill stage k+2 (all indices compile-time constants)
        if (tid == 0) {
            const int kl = k + STAGES - 1;
            if (kl < K_CHUNKS) {
                const int ls = kl % STAGES;
                const int lround = kl / STAGES;
                if (lround >= 1)
                    MBARRIER_WAIT_PARITY(emptyb + ls * 8, (lround - 1) & 1);
                MBARRIER_EXPECT_TX(fullb + ls * 8, STAGE_BYTES);
                CP_BULK16K(sb + ls * STAGE_BYTES, gAt + (size_t)kl * CHUNK_BYTES, fullb + ls * 8);
                CP_BULK16K(sb + ls * STAGE_BYTES + CHUNK_BYTES, gBt + (size_t)kl * CHUNK_BYTES, fullb + ls * 8);
            }
        }

        const int slot = k % STAGES;
        MBARRIER_WAIT_PARITY(fullb + slot * 8, (k / STAGES) & 1);

        const uint32_t stA = sb + slot * STAGE_BYTES;
        const uint32_t stB = stA + CHUNK_BYTES;

#pragma unroll
        for (int kk = 0; kk < 4; kk++) {          // four k16 steps per 128B chunk
            const uint32_t kU = kk * 2 + lmHi;

            uint32_t a[4][4];
#pragma unroll
            for (int i = 0; i < 4; i++) {
                uint32_t addr = stA + aOff[i] + ((kU ^ sxA[i]) << 4);
                LDMATRIX_X4(a[i][0], a[i][1], a[i][2], a[i][3], addr);
            }
            uint32_t b[2][4];
#pragma unroll
            for (int jp = 0; jp < 2; jp++) {
                uint32_t addr = stB + bOff[jp] + ((kU ^ sxB[jp]) << 4);
                LDMATRIX_X4(b[jp][0], b[jp][1], b[jp][2], b[jp][3], addr);
            }
#pragma unroll
            for (int i = 0; i < 4; i++) {
#pragma unroll
                for (int j = 0; j < 4; j++) {
                    int jp = j >> 1, h = j & 1;
                    MMA_16816_BF16(acc[i][j][0], acc[i][j][1], acc[i][j][2], acc[i][j][3],
                                   a[i][0], a[i][1], a[i][2], a[i][3],
                                   b[jp][h], b[jp][2 + h]);
                }
            }
        }
        if (lane == 0) MBARRIER_ARRIVE(emptyb + slot * 8);
    }

    // ---- epilogue: d = xs + ps - 2*cross ; out = -sqrt(max(d,0)) ----
    const int r0 = lane >> 2;        // 0..7
    const int cq = (lane & 3) * 2;   // 0,2,4,6

    float ps0[4], ps1[4];
#pragma unroll
    for (int j = 0; j < 4; j++) {
        int gc = bCol + wn * 32 + j * 8 + cq;
        ps0[j] = g_psq[gc];
        ps1[j] = g_psq[gc + 1];
    }

#pragma unroll
    for (int i = 0; i < 4; i++) {
#pragma unroll
        for (int h = 0; h < 2; h++) {
            int grow = bRow + wm * 64 + i * 16 + r0 + h * 8;
            float xs = g_xsq[grow];
            float* crow = C + (size_t)grow * P_ROWS + bCol + wn * 32;
#pragma unroll
            for (int j = 0; j < 4; j++) {
                float c0 = acc[i][j][h * 2 + 0];
                float c1 = acc[i][j][h * 2 + 1];
                float d0 = fmaf(-2.f, c0, xs + ps0[j]);
                float d1 = fmaf(-2.f, c1, xs + ps1[j]);
                float2 o;
                o.x = (d0 > 0.f) ? (-d0 * rsqrtf(d0)) : 0.f;
                o.y = (d1 > 0.f) ? (-d1 * rsqrtf(d1)) : 0.f;
                *reinterpret_cast<float2*>(crow + j * 8 + cq) = o;
            }
        }
    }
}

// ---------------- launch ----------------------------------------------------
extern "C" void kernel_launch(void* const* d_in, const int* in_sizes, int n_in,
                              void* d_out, int out_size) {
    const float* emb   = (const float*)d_in[0];  // [N, D]
    const float* proto = (const float*)d_in[1];  // [P, D]
    float* out = (float*)d_out;                  // [N, P]

    cudaFuncSetAttribute(gemm_mma_kernel,
                         cudaFuncAttributeMaxDynamicSharedMemorySize, SMEM_TOTAL);

    convert_all_kernel<<<(N_ROWS + P_ROWS) / 8, 256>>>(emb, proto);

    dim3 grid(P_ROWS / BN, N_ROWS / BM);  // (16, 512): columns fastest -> A reuse in L2
    gemm_mma_kernel<<<grid, 256, SMEM_TOTAL>>>(out);
}